// round 2
// baseline (speedup 1.0000x reference)
#include <cuda_runtime.h>
#include <cuda_bf16.h>

// RipsLayer: out[t] = ||X[i_t] - X[j_t]||, t in [0, 16384), D=3.
// Dense NxN distance matrix from the reference is dead work — only the
// gathered entries are computed.
//
// Inputs (metadata order):
//   d_in[0] = X       float32 [8192, 3]
//   d_in[1] = indices int32   [8192, 2, 2]  -> flattened pairs (i,j) per output
// Output:
//   d_out   = dgm     float32 [8192, 2]     (16384 floats)
//
// Each thread produces 4 consecutive outputs:
//  - 2 independent int4 loads fetch 4 (i,j) pairs (no per-pair dependent hops)
//  - 24 independent gathered float loads (MLP ~26/warp, under per-warp cap)
//  - 1 aligned float4 store

__global__ void rips_gather_dist4_kernel(const float* __restrict__ X,
                                         const int4* __restrict__ idx4,
                                         float4* __restrict__ out4,
                                         int total4) {
    int t = blockIdx.x * blockDim.x + threadIdx.x;
    if (t >= total4) return;

    // Two int4 loads = 4 (i,j) pairs, issued back-to-back (independent).
    int4 p0 = idx4[2 * t + 0];   // (i0, j0, i1, j1)
    int4 p1 = idx4[2 * t + 1];   // (i2, j2, i3, j3)

    int ia[4] = { p0.x * 3, p0.z * 3, p1.x * 3, p1.z * 3 };
    int ja[4] = { p0.y * 3, p0.w * 3, p1.y * 3, p1.w * 3 };

    // 24 independent gathers — compiler front-batches these (high MLP_p1).
    float ax[4], ay[4], az[4], bx[4], by[4], bz[4];
#pragma unroll
    for (int k = 0; k < 4; k++) {
        ax[k] = __ldg(&X[ia[k] + 0]);
        ay[k] = __ldg(&X[ia[k] + 1]);
        az[k] = __ldg(&X[ia[k] + 2]);
        bx[k] = __ldg(&X[ja[k] + 0]);
        by[k] = __ldg(&X[ja[k] + 1]);
        bz[k] = __ldg(&X[ja[k] + 2]);
    }

    float r[4];
#pragma unroll
    for (int k = 0; k < 4; k++) {
        float dx = ax[k] - bx[k];
        float dy = ay[k] - by[k];
        float dz = az[k] - bz[k];
        r[k] = sqrtf(fmaf(dx, dx, fmaf(dy, dy, dz * dz)));
    }

    out4[t] = make_float4(r[0], r[1], r[2], r[3]);
}

extern "C" void kernel_launch(void* const* d_in, const int* in_sizes, int n_in,
                              void* d_out, int out_size) {
    const float* X    = (const float*)d_in[0];
    const int4*  idx4 = (const int4*)d_in[1];   // 2 int4 per 4 outputs
    float4*      out4 = (float4*)d_out;

    int total4 = out_size / 4;                  // 4096 threads
    int threads = 128;
    int blocks = (total4 + threads - 1) / threads;  // 32 blocks
    rips_gather_dist4_kernel<<<blocks, threads>>>(X, idx4, out4, total4);
}

// round 3
// speedup vs baseline: 1.0518x; 1.0518x over previous
#include <cuda_runtime.h>
#include <cuda_bf16.h>

// RipsLayer: out[t] = ||X[i_t] - X[j_t]||, t in [0, 16384), D=3.
// One output per thread (R2 showed batching shrinks SM coverage and regresses).
// Grid shaped to cover all 148 SMs: 256 blocks x 64 threads.
//
// Inputs (metadata order):
//   d_in[0] = X       float32 [8192, 3]
//   d_in[1] = indices int32   [8192, 2, 2] -> flattened (i,j) per output
// Output:
//   d_out   = dgm     float32 [8192, 2]    (16384 floats)

__global__ void __launch_bounds__(64, 16)
rips_gather_dist_kernel(const float* __restrict__ X,
                        const int2* __restrict__ idx,
                        float* __restrict__ out) {
    int t = blockIdx.x * 64 + threadIdx.x;   // grid exactly covers 16384

    int2 ij = idx[t];
    int i3 = ij.x * 3;
    int j3 = ij.y * 3;

    float ax = __ldg(&X[i3 + 0]);
    float ay = __ldg(&X[i3 + 1]);
    float az = __ldg(&X[i3 + 2]);
    float bx = __ldg(&X[j3 + 0]);
    float by = __ldg(&X[j3 + 1]);
    float bz = __ldg(&X[j3 + 2]);

    float dx = ax - bx;
    float dy = ay - by;
    float dz = az - bz;

    out[t] = sqrtf(fmaf(dx, dx, fmaf(dy, dy, dz * dz)));
}

extern "C" void kernel_launch(void* const* d_in, const int* in_sizes, int n_in,
                              void* d_out, int out_size) {
    const float* X   = (const float*)d_in[0];
    const int2*  idx = (const int2*)d_in[1];
    float*       out = (float*)d_out;

    // 16384 outputs exactly: 256 blocks x 64 threads spreads over all SMs.
    rips_gather_dist_kernel<<<256, 64>>>(X, idx, out);
}

// round 4
// speedup vs baseline: 1.0628x; 1.0105x over previous
#include <cuda_runtime.h>
#include <cuda_bf16.h>

// RipsLayer: out[t] = ||X[i_t] - X[j_t]||, t in [0, 16384), D=3.
//
// Latency-floor kernel (issue 1.6%, DRAM 0.6%): the irreducible structure is
// the 2-hop chain idx-load -> gathered X loads. This round: 2 outputs per
// thread, 8192 threads as 128 blocks x 64 threads (full SM coverage kept,
// unlike the failed 32-block R2). Per thread: one coalesced int4 idx load
// (2 pairs), 12 independent gathers, one float2 store.
//
// Inputs (metadata order):
//   d_in[0] = X       float32 [8192, 3]
//   d_in[1] = indices int32   [8192, 2, 2] -> flattened (i,j) per output
// Output:
//   d_out   = dgm     float32 [8192, 2]    (16384 floats)

__global__ void __launch_bounds__(64, 16)
rips_gather_dist2_kernel(const float* __restrict__ X,
                         const int4* __restrict__ idx4,
                         float2* __restrict__ out2) {
    int t = blockIdx.x * 64 + threadIdx.x;   // 8192 threads exactly

    int4 p = idx4[t];                        // (i0, j0, i1, j1)
    int i0 = p.x * 3, j0 = p.y * 3;
    int i1 = p.z * 3, j1 = p.w * 3;

    // 12 independent gathers, all issued before any consumer.
    float a0x = __ldg(&X[i0 + 0]);
    float a0y = __ldg(&X[i0 + 1]);
    float a0z = __ldg(&X[i0 + 2]);
    float b0x = __ldg(&X[j0 + 0]);
    float b0y = __ldg(&X[j0 + 1]);
    float b0z = __ldg(&X[j0 + 2]);
    float a1x = __ldg(&X[i1 + 0]);
    float a1y = __ldg(&X[i1 + 1]);
    float a1z = __ldg(&X[i1 + 2]);
    float b1x = __ldg(&X[j1 + 0]);
    float b1y = __ldg(&X[j1 + 1]);
    float b1z = __ldg(&X[j1 + 2]);

    float d0x = a0x - b0x, d0y = a0y - b0y, d0z = a0z - b0z;
    float d1x = a1x - b1x, d1y = a1y - b1y, d1z = a1z - b1z;

    float r0 = sqrtf(fmaf(d0x, d0x, fmaf(d0y, d0y, d0z * d0z)));
    float r1 = sqrtf(fmaf(d1x, d1x, fmaf(d1y, d1y, d1z * d1z)));

    out2[t] = make_float2(r0, r1);
}

extern "C" void kernel_launch(void* const* d_in, const int* in_sizes, int n_in,
                              void* d_out, int out_size) {
    const float* X    = (const float*)d_in[0];
    const int4*  idx4 = (const int4*)d_in[1];   // one int4 = 2 (i,j) pairs
    float2*      out2 = (float2*)d_out;

    // 8192 threads exactly: 128 blocks x 64 threads, full SM coverage.
    rips_gather_dist2_kernel<<<128, 64>>>(X, idx4, out2);
}